// round 17
// baseline (speedup 1.0000x reference)
#include <cuda_runtime.h>
#include <cuda_bf16.h>
#include <cuda_fp16.h>
#include <math.h>
#include <stdint.h>

// ---------------- problem constants ----------------
#define D_MODEL  768
#define N_LAYERS 2
#define D_STATE  16
#define VOCAB    32000
#define D_INNER  1536            // 2*D_MODEL
#define BATCH    2
#define SEQ      2048
#define NTOK     (BATCH*SEQ)     // 4096
#define LN_EPS   1e-5f
#define NCOMB    4608            // [x_ssm | gate | dt] combined width
#define SPLIT_COL 3072           // softplus region starts here

// ---------------- scratch ----------------
__device__ static float g_x  [NTOK * D_MODEL];
__device__ static float g_xpc[NTOK * NCOMB];     // combined xp|gate|dt
__device__ static float g_Bm [NTOK * D_STATE];
__device__ static float g_Cm [NTOK * D_STATE];
__device__ static float g_o  [NTOK * D_MODEL];
// fp16 operands (ALL GEMMs plain fp16)
__device__ static __half g_xf16[NTOK * D_MODEL];
__device__ static __half g_yf16[NTOK * D_INNER];
__device__ static __half g_wcf16[N_LAYERS * NCOMB * D_MODEL];   // [W_in|W_dt]
__device__ static __half g_wof16[N_LAYERS * D_MODEL * D_INNER];
__device__ static __half g_ef16 [VOCAB * D_MODEL];

// ======================= helpers =======================
#define SW128X(o) ((o) ^ (((o) >> 3) & 0x70))

__device__ __forceinline__ uint32_t s2u(const void* p) {
    uint32_t a;
    asm("{ .reg .u64 t; cvta.to.shared.u64 t, %1; cvt.u32.u64 %0, t; }"
        : "=r"(a) : "l"(p));
    return a;
}

__device__ __forceinline__ void ldsm4(uint32_t* r, uint32_t addr) {
    asm volatile("ldmatrix.sync.aligned.m8n8.x4.shared.b16 {%0,%1,%2,%3}, [%4];"
                 : "=r"(r[0]), "=r"(r[1]), "=r"(r[2]), "=r"(r[3]) : "r"(addr));
}

__device__ __forceinline__ void mma_fp16(float* c, const uint32_t* a,
                                         uint32_t b0, uint32_t b1) {
    asm volatile(
        "mma.sync.aligned.m16n8k16.row.col.f32.f16.f16.f32 "
        "{%0,%1,%2,%3}, {%4,%5,%6,%7}, {%8,%9}, {%0,%1,%2,%3};"
        : "+f"(c[0]), "+f"(c[1]), "+f"(c[2]), "+f"(c[3])
        : "r"(a[0]), "r"(a[1]), "r"(a[2]), "r"(a[3]), "r"(b0), "r"(b1));
}

__device__ __forceinline__ void cp16(uint32_t saddr, const void* gaddr) {
    asm volatile("cp.async.ca.shared.global [%0], [%1], 16;"
                 :: "r"(saddr), "l"(gaddr) : "memory");
}

__device__ __forceinline__ uint32_t pack_hf2(float a, float b) {
    __half2 t = __floats2half2_rn(a, b);
    return *(uint32_t*)&t;
}

// ===== plain fp16 GEMM: C = A @ B^T, 3-stage pipeline, 2 CTAs/SM =====
// Tile 128x128, K-chunk 64, stage = 32KB, 3 stages = 96KB (192KB/SM <= 228KB
// so occupancy stays at 2 CTAs/SM; KCH and barrier count unchanged vs 2-stage).
// mode 1: softplus/clip for columns >= SPLIT_COL (biases at c-SPLIT_COL).
#define FP_A   0
#define FP_B   16384
#define FPSTG  32768
#define GEMM16_SMEM (3 * FPSTG)     // 98304

__global__ void __launch_bounds__(256, 2)
gemm_fp16(const __half* __restrict__ A, const __half* __restrict__ B,
          float* __restrict__ C, int M, int N, int K,
          int mode, const float* __restrict__ eb1, const float* __restrict__ eb2) {
    extern __shared__ char smc[];
    const uint32_t sb = s2u(smc);
    const int tid = threadIdx.x;
    const int wid = tid >> 5, lid = tid & 31;
    const int wm = wid & 1, wn = wid >> 1;          // warp grid 2(M) x 4(N)
    const int bm = blockIdx.x * 128, bn = blockIdx.y * 128;

    const int rin = lid & 7;
    const uint32_t xr = (uint32_t)rin << 4;
    const int amat = lid >> 3;
    const uint32_t aKq = (uint32_t)(amat >> 1) * 16;
    uint32_t aRow[4];
#pragma unroll
    for (int mt = 0; mt < 4; mt++)
        aRow[mt] = (uint32_t)(wm * 64 + mt * 16 + (amat & 1) * 8 + rin) * 128;
    const int bpair = lid >> 4, bsub = (lid >> 3) & 1;
    const uint32_t bKq = (uint32_t)bsub * 16;
    uint32_t bRow[2];
#pragma unroll
    for (int p = 0; p < 2; p++)
        bRow[p] = (uint32_t)(wn * 32 + p * 16 + bpair * 8 + rin) * 128;

    const int grow = tid >> 1;
    const int gch0 = (tid & 1) * 4;
    uint32_t sOff[4];
#pragma unroll
    for (int j = 0; j < 4; j++)
        sOff[j] = SW128X((uint32_t)grow * 128 + (uint32_t)(gch0 + j) * 16);

    const __half* gA = A + (size_t)(bm + grow) * K + gch0 * 8;
    const __half* gB = B + (size_t)(bn + grow) * K + gch0 * 8;

    float acc[4][4][4];
#pragma unroll
    for (int mt = 0; mt < 4; mt++)
#pragma unroll
        for (int nt = 0; nt < 4; nt++)
#pragma unroll
            for (int i = 0; i < 4; i++) acc[mt][nt][i] = 0.f;

    const int NC = K / 64;

    // prologue: chunks 0,1 -> stages 0,1
#pragma unroll
    for (int s = 0; s < 2; s++) {
        const uint32_t st = sb + (uint32_t)s * FPSTG;
        const int k0 = s * 64;
#pragma unroll
        for (int j = 0; j < 4; j++) {
            cp16(st + FP_A + sOff[j], gA + k0 + j * 8);
            cp16(st + FP_B + sOff[j], gB + k0 + j * 8);
        }
        asm volatile("cp.async.commit_group;" ::: "memory");
    }

    int stg = 0;                                 // = c % 3
    for (int c = 0; c < NC; c++) {
        if (c + 2 < NC) {
            int s2 = stg + 2; if (s2 >= 3) s2 -= 3;
            const uint32_t st2 = sb + (uint32_t)s2 * FPSTG;
            const int k2 = (c + 2) * 64;
#pragma unroll
            for (int j = 0; j < 4; j++) {
                cp16(st2 + FP_A + sOff[j], gA + k2 + j * 8);
                cp16(st2 + FP_B + sOff[j], gB + k2 + j * 8);
            }
            asm volatile("cp.async.commit_group;" ::: "memory");
            asm volatile("cp.async.wait_group 2;" ::: "memory");
        } else if (c + 1 < NC) {
            asm volatile("cp.async.wait_group 1;" ::: "memory");
        } else {
            asm volatile("cp.async.wait_group 0;" ::: "memory");
        }
        __syncthreads();

        const uint32_t st = sb + (uint32_t)stg * FPSTG;
#pragma unroll
        for (int ks = 0; ks < 4; ks++) {
            const uint32_t aoff = (((uint32_t)ks * 32 + aKq) ^ xr);
            const uint32_t boff = (((uint32_t)ks * 32 + bKq) ^ xr);
            uint32_t ah[4][4], bb[2][4];
#pragma unroll
            for (int mt = 0; mt < 4; mt++)
                ldsm4(ah[mt], st + FP_A + aRow[mt] + aoff);
#pragma unroll
            for (int p = 0; p < 2; p++)
                ldsm4(bb[p], st + FP_B + bRow[p] + boff);
#pragma unroll
            for (int mt = 0; mt < 4; mt++)
#pragma unroll
                for (int nt = 0; nt < 4; nt++)
                    mma_fp16(acc[mt][nt], ah[mt],
                             bb[nt >> 1][(nt & 1) * 2], bb[nt >> 1][(nt & 1) * 2 + 1]);
        }
        __syncthreads();   // stage consumed; overwritten at iter c+1's issue
        if (++stg == 3) stg = 0;
    }

    const int gid = lid >> 2, tig = lid & 3;
#pragma unroll
    for (int mt = 0; mt < 4; mt++) {
#pragma unroll
        for (int nt = 0; nt < 4; nt++) {
            int r0 = bm + wm * 64 + mt * 16 + gid;
            int c0 = bn + wn * 32 + nt * 8 + tig * 2;
            float v[4] = {acc[mt][nt][0], acc[mt][nt][1],
                          acc[mt][nt][2], acc[mt][nt][3]};
            if (mode == 1 && c0 >= SPLIT_COL) {
                int cb = c0 - SPLIT_COL;
                float bb0 = eb1[cb] + eb2[cb];
                float bb1 = eb1[cb + 1] + eb2[cb + 1];
#pragma unroll
                for (int i = 0; i < 4; i++) {
                    float t = v[i] + ((i & 1) ? bb1 : bb0);
                    float sp = (t > 20.f) ? t : log1pf(expf(t));
                    v[i] = fminf(fmaxf(sp, 0.f), 1.f);
                }
            }
            *(float2*)&C[(size_t)r0 * N + c0]       = make_float2(v[0], v[1]);
            *(float2*)&C[(size_t)(r0 + 8) * N + c0] = make_float2(v[2], v[3]);
        }
    }
}

// ------------- vectorized fp32 -> fp16 convert ----------------
__global__ void conv_fp16_kernel(const float* __restrict__ src,
                                 __half* __restrict__ dst, int n4) {
    int i = blockIdx.x * 256 + threadIdx.x;
    if (i < n4) {
        float4 v = ((const float4*)src)[i];
        ((uint2*)dst)[i] = make_uint2(pack_hf2(v.x, v.y), pack_hf2(v.z, v.w));
    }
}

// ---------------- embedding gather (+ fp16 emit) ----------------
__global__ void embed_kernel(const int* __restrict__ ids,
                             const float* __restrict__ emb,
                             float* __restrict__ x,
                             __half* __restrict__ xf16) {
    int row = blockIdx.x;
    int id  = ids[row];
    float4 v = ((const float4*)(emb + (size_t)id * D_MODEL))[threadIdx.x];
    ((float4*)(x + (size_t)row * D_MODEL))[threadIdx.x] = v;
    ((uint2*)(xf16 + (size_t)row * D_MODEL))[threadIdx.x] =
        make_uint2(pack_hf2(v.x, v.y), pack_hf2(v.z, v.w));
}

// ---------------- skinny GEMM for B/C projections (N=16 each) ----------------
__global__ __launch_bounds__(256)
void bc_gemm(const float* __restrict__ x, const float* __restrict__ Wb,
             const float* __restrict__ Wc, float* __restrict__ Bm,
             float* __restrict__ Cm) {
    __shared__ float xs[8][D_MODEL];
    int row0 = blockIdx.x * 8;
    const float4* xg = (const float4*)(x + (size_t)row0 * D_MODEL);
    float4* xsv = (float4*)xs;
    for (int i = threadIdx.x; i < 8 * D_MODEL / 4; i += 256) xsv[i] = xg[i];
    __syncthreads();

    int r = threadIdx.x >> 5;
    int c = threadIdx.x & 31;
    const float* W = (c < 16) ? (Wb + (size_t)c * D_MODEL)
                              : (Wc + (size_t)(c - 16) * D_MODEL);
    const float4* Wv = (const float4*)W;
    const float4* xr = (const float4*)xs[r];
    float s = 0.f;
#pragma unroll 4
    for (int k = 0; k < D_MODEL / 4; k++) {
        float4 w = Wv[k], v = xr[k];
        s += w.x * v.x + w.y * v.y + w.z * v.z + w.w * v.w;
    }
    if (c < 16) Bm[(size_t)(row0 + r) * D_STATE + c]        = s;
    else        Cm[(size_t)(row0 + r) * D_STATE + (c - 16)] = s;
}

// ======== SSM scan: TCH=32 double-buffered + FUSED gate/sigmoid/fp16 emit ========
// Dynamic SMEM (57,344 B > 48KB static cap) keeps TCH=32 — round-12's fusion
// regression came from halving TCH, not from the fusion itself (round-13 A/B).
// Math identical to the old scan + gate_mul chain.
#define TCH 32
#define SCAN_SMEM (2 * (3 * TCH * 64 + 2 * TCH * 16) * 4)   // 57344

__global__ void __launch_bounds__(128)
ssm_scan(const float* __restrict__ xpc,
         const float* __restrict__ Bm, const float* __restrict__ Cm,
         const float* __restrict__ Amat, const float* __restrict__ Dvec,
         __half* __restrict__ yf16) {
    extern __shared__ float sms[];
    float*  xp_s = sms;                          // [2][TCH][64]
    float*  dt_s = xp_s + 2 * TCH * 64;
    float*  gt_s = dt_s + 2 * TCH * 64;
    float4* B_s  = (float4*)(gt_s + 2 * TCH * 64);   // [2][TCH][4]
    float4* C_s  = B_s + 2 * TCH * 4;

    const int tid = threadIdx.x;
    const int wid = tid >> 5, lid = tid & 31;
    const int ch   = wid * 16 + (lid & 15);      // 0..63 local channel
    const int half = lid >> 4;                   // states [0,8) or [8,16)
    const int d0 = blockIdx.x * 64;
    const int d  = d0 + ch;
    const int b  = blockIdx.y;

    float Ar[8], h[8];
#pragma unroll
    for (int j = 0; j < 8; j++) {
        Ar[j] = Amat[(size_t)d * D_STATE + half * 8 + j];
        h[j]  = 0.f;
    }
    const float Dd = Dvec[d];

    const int tt0 = tid >> 4;            // 0..7
    const int seg = (tid & 15) * 4;      // float offset within 64-ch row

    auto issue_chunk = [&](int buf, int tc) {
#pragma unroll
        for (int r = 0; r < 4; r++) {
            int tt = tt0 + r * 8;
            size_t row = (size_t)b * SEQ + tc + tt;
            cp16(s2u(&xp_s[(buf * TCH + tt) * 64 + seg]),
                 xpc + row * NCOMB + d0 + seg);
            cp16(s2u(&gt_s[(buf * TCH + tt) * 64 + seg]),
                 xpc + row * NCOMB + D_INNER + d0 + seg);
            cp16(s2u(&dt_s[(buf * TCH + tt) * 64 + seg]),
                 xpc + row * NCOMB + SPLIT_COL + d0 + seg);
        }
        size_t bcbase = ((size_t)b * SEQ + tc) * D_STATE;   // 512 floats/chunk
        cp16(s2u((float*)(B_s + buf * TCH * 4) + tid * 4), Bm + bcbase + tid * 4);
        cp16(s2u((float*)(C_s + buf * TCH * 4) + tid * 4), Cm + bcbase + tid * 4);
        asm volatile("cp.async.commit_group;" ::: "memory");
    };

    issue_chunk(0, 0);
    const int NCH = SEQ / TCH;
    for (int c = 0; c < NCH; c++) {
        const int buf = c & 1;
        if (c + 1 < NCH) {
            issue_chunk(buf ^ 1, (c + 1) * TCH);
            asm volatile("cp.async.wait_group 1;" ::: "memory");
        } else {
            asm volatile("cp.async.wait_group 0;" ::: "memory");
        }
        __syncthreads();

        const int tcg = c * TCH;
#pragma unroll 4
        for (int tt = 0; tt < TCH; tt++) {
            float u  = xp_s[(buf * TCH + tt) * 64 + ch];
            float dv = dt_s[(buf * TCH + tt) * 64 + ch];
            float4 Bv0 = B_s[(buf * TCH + tt) * 4 + half * 2];
            float4 Bv1 = B_s[(buf * TCH + tt) * 4 + half * 2 + 1];
            float4 Cv0 = C_s[(buf * TCH + tt) * 4 + half * 2];
            float4 Cv1 = C_s[(buf * TCH + tt) * 4 + half * 2 + 1];
            float bs[8] = {Bv0.x, Bv0.y, Bv0.z, Bv0.w, Bv1.x, Bv1.y, Bv1.z, Bv1.w};
            float cs[8] = {Cv0.x, Cv0.y, Cv0.z, Cv0.w, Cv1.x, Cv1.y, Cv1.z, Cv1.w};
            float u01 = 0.1f * u;
            float adt = 0.1f * dv;
            float p0 = 0.f, p1 = 0.f;
#pragma unroll
            for (int j = 0; j < 8; j++) {
                float hv = h[j];
                hv = fmaf(hv * Ar[j], adt, fmaf(bs[j], u01, hv));
                h[j] = hv;
                float p = hv * cs[j];
                if (j & 1) p1 += p; else p0 += p;
            }
            float part = p0 + p1;
            float tot = part + __shfl_xor_sync(0xffffffffu, part, 16);
            if (!half) {
                float g = gt_s[(buf * TCH + tt) * 64 + ch];
                float v = (Dd * u + tot) * (1.f / (1.f + expf(-g)));
                yf16[((size_t)b * SEQ + tcg + tt) * D_INNER + d] = __float2half(v);
            }
        }
        __syncthreads();
    }
}

// -------- layernorm: out = post? + LN(in + res?) * g + b (+ fp16 emit) --------
__device__ __forceinline__ float block_reduce(float v, float* red) {
    for (int o = 16; o > 0; o >>= 1) v += __shfl_down_sync(0xffffffffu, v, o);
    if ((threadIdx.x & 31) == 0) red[threadIdx.x >> 5] = v;
    __syncthreads();
    float t = 0.f;
#pragma unroll
    for (int w = 0; w < 8; w++) t += red[w];
    return t;
}

__global__ __launch_bounds__(256)
void ln_kernel(const float* __restrict__ in, const float* __restrict__ res,
               const float* __restrict__ post,
               const float* __restrict__ g, const float* __restrict__ b,
               float* __restrict__ out, __half* __restrict__ of16) {
    __shared__ float red[8];
    const int row = blockIdx.x;
    const int t   = threadIdx.x;
    float v[3], pv[3];
    float s = 0.f;
#pragma unroll
    for (int i = 0; i < 3; i++) {
        int c = t + i * 256;
        float x = in[(size_t)row * D_MODEL + c];
        if (res) x += res[(size_t)row * D_MODEL + c];
        pv[i] = post ? post[(size_t)row * D_MODEL + c] : 0.f;
        v[i] = x;
        s += x;
    }
    float tot = block_reduce(s, red);
    float mu = tot * (1.f / D_MODEL);
    __syncthreads();
    float q = 0.f;
#pragma unroll
    for (int i = 0; i < 3; i++) {
        float dd = v[i] - mu;
        q += dd * dd;
    }
    float qtot = block_reduce(q, red);
    float rs = rsqrtf(qtot * (1.f / D_MODEL) + LN_EPS);
#pragma unroll
    for (int i = 0; i < 3; i++) {
        int c = t + i * 256;
        float o = pv[i] + (v[i] - mu) * rs * g[c] + b[c];
        size_t idx = (size_t)row * D_MODEL + c;
        out[idx] = o;
        of16[idx] = __float2half(o);
    }
}

// ---------------- launch ----------------
extern "C" void kernel_launch(void* const* d_in, const int* in_sizes, int n_in,
                              void* d_out, int out_size) {
    const int*   input_ids = (const int*)  d_in[0];
    const float* emb       = (const float*)d_in[1];
    const float* W_in      = (const float*)d_in[2];   // [2, 3072, 768]
    const float* W_dt      = (const float*)d_in[3];   // [2, 1536, 768]
    const float* b_dt      = (const float*)d_in[4];
    const float* dt_bias   = (const float*)d_in[5];
    const float* W_B       = (const float*)d_in[6];
    const float* W_C       = (const float*)d_in[7];
    const float* Amat      = (const float*)d_in[8];
    const float* Dvec      = (const float*)d_in[9];
    const float* W_out     = (const float*)d_in[10];  // [2, 768, 1536]
    const float* ln_g      = (const float*)d_in[11];
    const float* ln_b      = (const float*)d_in[12];
    const float* fin_g     = (const float*)d_in[13];
    const float* fin_b     = (const float*)d_in[14];
    float* logits = (float*)d_out;                    // [4096, 32000]

    float *x, *xpc, *Bm, *Cm, *o;
    __half *xf16, *yf16, *wcf16, *wof16, *ef16;
    cudaGetSymbolAddress((void**)&x,   g_x);
    cudaGetSymbolAddress((void**)&xpc, g_xpc);
    cudaGetSymbolAddress((void**)&Bm,  g_Bm);
    cudaGetSymbolAddress((void**)&Cm,  g_Cm);
    cudaGetSymbolAddress((void**)&o,   g_o);
    cudaGetSymbolAddress((void**)&xf16, g_xf16);
    cudaGetSymbolAddress((void**)&yf16, g_yf16);
    cudaGetSymbolAddress((void**)&wcf16, g_wcf16);
    cudaGetSymbolAddress((void**)&wof16, g_wof16);
    cudaGetSymbolAddress((void**)&ef16, g_ef16);

    cudaFuncSetAttribute(gemm_fp16, cudaFuncAttributeMaxDynamicSharedMemorySize,
                         GEMM16_SMEM);
    cudaFuncSetAttribute(ssm_scan, cudaFuncAttributeMaxDynamicSharedMemorySize,
                         SCAN_SMEM);

    embed_kernel<<<NTOK, D_MODEL / 4>>>(input_ids, emb, x, xf16);

    // hoisted fp16 weight converts (combined [W_in | W_dt] per layer)
    for (int l = 0; l < N_LAYERS; l++) {
        int n4 = 2 * D_INNER * D_MODEL / 4;
        conv_fp16_kernel<<<(n4 + 255) / 256, 256>>>(
            W_in + (size_t)l * 2 * D_INNER * D_MODEL,
            wcf16 + (size_t)l * NCOMB * D_MODEL, n4);
        n4 = D_INNER * D_MODEL / 4;
        conv_fp16_kernel<<<(n4 + 255) / 256, 256>>>(
            W_dt + (size_t)l * D_INNER * D_MODEL,
            wcf16 + (size_t)l * NCOMB * D_MODEL + (size_t)SPLIT_COL * D_MODEL, n4);
    }
    {
        int n4 = N_LAYERS * D_MODEL * D_INNER / 4;
        conv_fp16_kernel<<<(n4 + 255) / 256, 256>>>(W_out, wof16, n4);
        n4 = VOCAB * D_MODEL / 4;
        conv_fp16_kernel<<<(n4 + 255) / 256, 256>>>(emb, ef16, n4);
    }

    for (int l = 0; l < N_LAYERS; l++) {
        const size_t oWc = (size_t)l * NCOMB * D_MODEL;
        const size_t oWo = (size_t)l * D_MODEL * D_INNER;
        const float* bd = b_dt    + (size_t)l * D_INNER;
        const float* db = dt_bias + (size_t)l * D_INNER;
        const float* Wb = W_B   + (size_t)l * D_STATE * D_MODEL;
        const float* Wc = W_C   + (size_t)l * D_STATE * D_MODEL;
        const float* Al = Amat  + (size_t)l * D_INNER * D_STATE;
        const float* Dl = Dvec  + (size_t)l * D_INNER;
        const float* lg = ln_g  + (size_t)l * D_MODEL;
        const float* lb = ln_b  + (size_t)l * D_MODEL;

        // [xp | gate | dt] = x @ [W_in ; W_dt]^T : [4096, 4608], softplus fused
        gemm_fp16<<<dim3(NTOK / 128, NCOMB / 128), 256, GEMM16_SMEM>>>(
            xf16, wcf16 + oWc, xpc, NTOK, NCOMB, D_MODEL, 1, bd, db);
        bc_gemm<<<NTOK / 8, 256>>>(x, Wb, Wc, Bm, Cm);
        // scan + fused gate/sigmoid/fp16 emit -> yf16
        ssm_scan<<<dim3(D_INNER / 64, BATCH), 128, SCAN_SMEM>>>(
            xpc, Bm, Cm, Al, Dl, yf16);
        // o = (y*gate) @ W_out^T : [4096, 768], K=1536
        gemm_fp16<<<dim3(NTOK / 128, D_MODEL / 128), 256, GEMM16_SMEM>>>(
            yf16, wof16 + oWo, o, NTOK, D_MODEL, D_INNER, 0, nullptr, nullptr);
        // x <- x + LN(o + x)  (emit fp16 x for next layer's GEMMs)
        ln_kernel<<<NTOK, 256>>>(o, x, x, lg, lb, x, xf16);
    }

    // final LN (emit fp16 x for logits GEMM)
    ln_kernel<<<NTOK, 256>>>(x, nullptr, nullptr, fin_g, fin_b, x, xf16);
    // logits = x @ emb^T : [4096, 32000]  (plain fp16, 3-stage pipeline)
    gemm_fp16<<<dim3(NTOK / 128, VOCAB / 128), 256, GEMM16_SMEM>>>(
        xf16, ef16, logits, NTOK, VOCAB, D_MODEL, 0, nullptr, nullptr);
}